// round 17
// baseline (speedup 1.0000x reference)
#include <cuda_runtime.h>
#include <math.h>
#include <cstdint>

#define BB 2
#define NN 2048
#define DM 512
#define NH 8
#define HD 64
#define TOPK 64
#define BH (BB*NH)       // 16
#define M_TOT (BB*NN)    // 4096
#define SCALEF 0.125f

// ---------------- scratch (static __device__ per allocation rules) ----------
__device__ float g_Qh[BH*NN*HD];            // [bh][n][d]  (Q pre-scaled by 1/8)
__device__ float g_Kh[BH*NN*HD];
__device__ float g_Vh[BH*NN*HD];
__device__ float g_S[(size_t)BH*NN*NN];     // raw scores 256MB
__device__ float g_H[M_TOT*DM];             // merged-head attn output

// ---------------------------------------------------------------------------
// 64x128-tile fp32 GEMM, 4x8 micro-tile, BK=16, 256 threads, double-buffered.
// Same k-order per output as the 128-row version => bit-identical numerics.
// mode 0: fused QKV (which=bx>>2, o0=(bx&3)*128), head-split out, Q*SCALE.
//         grid (12, 64).
// mode 1: out-projection from g_H, row-major out. grid (4, 64) = 256 blocks.
// ---------------------------------------------------------------------------
__global__ __launch_bounds__(256)
void gemm64(const float* __restrict__ X0, const float* __restrict__ X1,
            const float* __restrict__ X2,
            const float* __restrict__ W0, const float* __restrict__ W1,
            const float* __restrict__ W2,
            const float* __restrict__ b0, const float* __restrict__ b1,
            const float* __restrict__ b2,
            float* __restrict__ outp, int mode)
{
    __shared__ float XsT[2][16][68];    // [k][m], 64 rows pad 4
    __shared__ float WsT[2][16][132];   // [k][o], 128 rows pad 4

    const int tid = threadIdx.x;
    const int tx = tid & 15, ty = tid >> 4;
    const int m0 = blockIdx.y * 64;

    int which = 0, o0 = 0;
    const float *X, *W, *bias;
    if (mode == 0) {
        which = blockIdx.x >> 2;
        o0 = (blockIdx.x & 3) * 128;
        X    = (which == 0) ? X0 : (which == 1) ? X1 : X2;
        W    = (which == 0) ? W0 : (which == 1) ? W1 : W2;
        bias = (which == 0) ? b0 : (which == 1) ? b1 : b2;
    } else {
        o0 = blockIdx.x * 128;
        X = g_H; W = W0; bias = b0;
    }

    const int xr_r  = tid >> 2;          // 0..63   (X tile row)
    const int xr_c4 = (tid & 3) * 4;     // 0,4,8,12
    const int wr_r  = tid >> 2;          // base row for W (2 iters: +0, +64)
    const int wr_c4 = (tid & 3) * 4;

    float acc[4][8];
#pragma unroll
    for (int i = 0; i < 4; i++)
#pragma unroll
        for (int j = 0; j < 8; j++) acc[i][j] = 0.f;

    float4 xrv, wrv[2];
    // preload chunk 0
    xrv = *(const float4*)&X[(size_t)(m0 + xr_r) * DM + xr_c4];
#pragma unroll
    for (int j = 0; j < 2; j++)
        wrv[j] = *(const float4*)&W[(size_t)(o0 + wr_r + j * 64) * DM + wr_c4];
    XsT[0][xr_c4 + 0][xr_r] = xrv.x; XsT[0][xr_c4 + 1][xr_r] = xrv.y;
    XsT[0][xr_c4 + 2][xr_r] = xrv.z; XsT[0][xr_c4 + 3][xr_r] = xrv.w;
#pragma unroll
    for (int j = 0; j < 2; j++) {
        int r = wr_r + j * 64;
        WsT[0][wr_c4 + 0][r] = wrv[j].x; WsT[0][wr_c4 + 1][r] = wrv[j].y;
        WsT[0][wr_c4 + 2][r] = wrv[j].z; WsT[0][wr_c4 + 3][r] = wrv[j].w;
    }
    __syncthreads();

    int p = 0;
    for (int k0 = 0; k0 < DM; k0 += 16) {
        const int kn = k0 + 16;
        if (kn < DM) {
            xrv = *(const float4*)&X[(size_t)(m0 + xr_r) * DM + kn + xr_c4];
#pragma unroll
            for (int j = 0; j < 2; j++)
                wrv[j] = *(const float4*)&W[(size_t)(o0 + wr_r + j * 64) * DM + kn + wr_c4];
        }
#pragma unroll
        for (int kk = 0; kk < 16; kk++) {
            float4 a0 = *(const float4*)&XsT[p][kk][ty * 4];
            float4 bv0 = *(const float4*)&WsT[p][kk][tx * 4];
            float4 bv1 = *(const float4*)&WsT[p][kk][64 + tx * 4];
            float a[4] = {a0.x, a0.y, a0.z, a0.w};
            float b[8] = {bv0.x, bv0.y, bv0.z, bv0.w, bv1.x, bv1.y, bv1.z, bv1.w};
#pragma unroll
            for (int i = 0; i < 4; i++)
#pragma unroll
                for (int j = 0; j < 8; j++) acc[i][j] += a[i] * b[j];
        }
        if (kn < DM) {
            int pn = p ^ 1;
            XsT[pn][xr_c4 + 0][xr_r] = xrv.x; XsT[pn][xr_c4 + 1][xr_r] = xrv.y;
            XsT[pn][xr_c4 + 2][xr_r] = xrv.z; XsT[pn][xr_c4 + 3][xr_r] = xrv.w;
#pragma unroll
            for (int j = 0; j < 2; j++) {
                int r = wr_r + j * 64;
                WsT[pn][wr_c4 + 0][r] = wrv[j].x; WsT[pn][wr_c4 + 1][r] = wrv[j].y;
                WsT[pn][wr_c4 + 2][r] = wrv[j].z; WsT[pn][wr_c4 + 3][r] = wrv[j].w;
            }
        }
        __syncthreads();
        p ^= 1;
    }

    const float sc = (mode == 0 && which == 0) ? SCALEF : 1.f;
#pragma unroll
    for (int i = 0; i < 4; i++) {
        int m = m0 + ty * 4 + i;
#pragma unroll
        for (int jg = 0; jg < 2; jg++) {
            int oc = o0 + ((jg == 0) ? tx * 4 : 64 + tx * 4);
            float4 v;
            v.x = (acc[i][jg * 4 + 0] + bias[oc + 0]) * sc;
            v.y = (acc[i][jg * 4 + 1] + bias[oc + 1]) * sc;
            v.z = (acc[i][jg * 4 + 2] + bias[oc + 2]) * sc;
            v.w = (acc[i][jg * 4 + 3] + bias[oc + 3]) * sc;
            if (mode == 0) {
                int b = m >> 11, n = m & (NN - 1);
                int h = oc >> 6, d = oc & 63;
                float* dst = (which == 0) ? g_Qh : (which == 1) ? g_Kh : g_Vh;
                *(float4*)&dst[(size_t)((b * NH + h) * NN + n) * HD + d] = v;
            } else {
                *(float4*)&outp[(size_t)m * DM + oc] = v;
            }
        }
    }
}

// ---------------------------------------------------------------------------
// Scores (round-5 proven, untouched): S = Qh @ Kh^T. 128x128 tiles,
// 8x8 micro-tile, 2 x BK=32 stages, __stcs streaming stores. grid (16,16,16).
// ---------------------------------------------------------------------------
__global__ __launch_bounds__(256)
void scores_kernel()
{
    __shared__ float QsT[32][132];
    __shared__ float KsT[32][132];

    const int bh = blockIdx.z;
    const int kx = blockIdx.x * 128;
    const int qy = blockIdx.y * 128;
    const int tid = threadIdx.x;
    const int tx = tid & 15, ty = tid >> 4;

    float acc[8][8];
#pragma unroll
    for (int i = 0; i < 8; i++)
#pragma unroll
        for (int j = 0; j < 8; j++) acc[i][j] = 0.f;

    for (int kb = 0; kb < HD; kb += 32) {
#pragma unroll
        for (int j = 0; j < 4; j++) {
            int i = tid + j * 256;
            int r = i >> 3, c4 = (i & 7) * 4;
            float4 qv = *(const float4*)&g_Qh[((size_t)bh * NN + qy + r) * HD + kb + c4];
            QsT[c4 + 0][r] = qv.x; QsT[c4 + 1][r] = qv.y;
            QsT[c4 + 2][r] = qv.z; QsT[c4 + 3][r] = qv.w;
            float4 kv = *(const float4*)&g_Kh[((size_t)bh * NN + kx + r) * HD + kb + c4];
            KsT[c4 + 0][r] = kv.x; KsT[c4 + 1][r] = kv.y;
            KsT[c4 + 2][r] = kv.z; KsT[c4 + 3][r] = kv.w;
        }
        __syncthreads();
#pragma unroll
        for (int kk = 0; kk < 32; kk++) {
            float4 a0 = *(const float4*)&QsT[kk][ty * 4];
            float4 a1 = *(const float4*)&QsT[kk][64 + ty * 4];
            float4 bv0 = *(const float4*)&KsT[kk][tx * 4];
            float4 bv1 = *(const float4*)&KsT[kk][64 + tx * 4];
            float a[8] = {a0.x, a0.y, a0.z, a0.w, a1.x, a1.y, a1.z, a1.w};
            float b[8] = {bv0.x, bv0.y, bv0.z, bv0.w, bv1.x, bv1.y, bv1.z, bv1.w};
#pragma unroll
            for (int i = 0; i < 8; i++)
#pragma unroll
                for (int j = 0; j < 8; j++) acc[i][j] += a[i] * b[j];
        }
        __syncthreads();
    }

#pragma unroll
    for (int i = 0; i < 8; i++) {
        int row = qy + ((i < 4) ? ty * 4 + i : 64 + ty * 4 + (i - 4));
#pragma unroll
        for (int jg = 0; jg < 2; jg++) {
            int col = kx + ((jg == 0) ? tx * 4 : 64 + tx * 4);
            float4 v = make_float4(acc[i][jg * 4 + 0], acc[i][jg * 4 + 1],
                                   acc[i][jg * 4 + 2], acc[i][jg * 4 + 3]);
            __stcs((float4*)&g_S[((size_t)bh * NN + row) * NN + col], v);
        }
    }
}

// ---------------------------------------------------------------------------
// WARP-PER-ROW topk + softmax + AV (round-16 proven, untouched).
// grid 4096 x 256.
// ---------------------------------------------------------------------------
__device__ __forceinline__ float key2float(unsigned k) {
    unsigned u = (k & 0x80000000u) ? (k & 0x7fffffffu) : ~k;
    return __uint_as_float(u);
}

__global__ __launch_bounds__(256)
void topk_av_warp(float* __restrict__ attn, int write_attn)
{
    const int wid  = threadIdx.x >> 5;
    const int lane = threadIdx.x & 31;
    const int row  = blockIdx.x * 8 + wid;    // bh*N + q
    const int bh   = row >> 11;
    const int q    = row & (NN - 1);

    __shared__ int   hist_s[8][256];
    __shared__ int   sidx_s[8][96];
    __shared__ float sw_s[8][96];
    __shared__ int   cnt_s[8];

    int*   hist = hist_s[wid];
    int*   sidx = sidx_s[wid];
    float* sw   = sw_s[wid];

    // ---- load 64 scores/lane as monotone uint keys (coalesced float4) ----
    const float4* Srow = (const float4*)&g_S[(size_t)row * NN];
    unsigned keys[64];
#pragma unroll
    for (int i = 0; i < 16; i++) {
        float4 v = __ldcs(&Srow[i * 32 + lane]);
        float f[4] = {v.x, v.y, v.z, v.w};
#pragma unroll
        for (int j = 0; j < 4; j++) {
            unsigned u = __float_as_uint(f[j]);
            keys[i * 4 + j] = (u & 0x80000000u) ? ~u : (u | 0x80000000u);
        }
    }
    if (lane == 0) cnt_s[wid] = 0;

    // ---- exact 64th-largest via 4 x 8-bit MSB radix passes (r5 frozen) ----
    unsigned prefix = 0;
    int kk = TOPK;
    for (int pass = 0; pass < 4; pass++) {
        const int shift = 24 - 8 * pass;
#pragma unroll
        for (int j = 0; j < 8; j++) hist[lane * 8 + j] = 0;
        __syncwarp();

        if (pass == 0) {
#pragma unroll
            for (int e = 0; e < 64; e++) {
                unsigned bin = keys[e] >> 24;
                unsigned mm = __match_any_sync(0xffffffffu, bin);
                if ((int)(__ffs(mm) - 1) == lane)
                    atomicAdd(&hist[bin], __popc(mm));
            }
        } else {
#pragma unroll
            for (int e = 0; e < 64; e++) {
                unsigned k = keys[e];
                unsigned hi = (k >> (31 - 8 * pass)) >> 1;
                if (hi == prefix) atomicAdd(&hist[(k >> shift) & 255u], 1);
            }
        }
        __syncwarp();

        int h[8], ls[8];
#pragma unroll
        for (int j = 0; j < 8; j++) h[j] = hist[lane * 8 + j];
        int tot = 0;
#pragma unroll
        for (int j = 7; j >= 0; j--) { tot += h[j]; ls[j] = tot; }
        int s = tot;
#pragma unroll
        for (int off = 1; off < 32; off <<= 1) {
            int t = __shfl_down_sync(0xffffffffu, s, off);
            if (lane + off < 32) s += t;
        }
        const int G = s - tot;
        int foundBin = -1, newkk = 0;
#pragma unroll
        for (int j = 0; j < 8; j++) {
            int ge = ls[j] + G;
            int gt = ge - h[j];
            if (ge >= kk && gt < kk && h[j] > 0) {
                foundBin = lane * 8 + j;
                newkk = kk - gt;
            }
        }
        unsigned bal = __ballot_sync(0xffffffffu, foundBin >= 0);
        int src = __ffs(bal) - 1;
        foundBin = __shfl_sync(0xffffffffu, foundBin, src);
        newkk    = __shfl_sync(0xffffffffu, newkk, src);
        prefix = (prefix << 8) | (unsigned)foundBin;
        kk = newkk;
        __syncwarp();
    }
    const unsigned kth = prefix;

    // ---- row max (key order == float order) ----
    unsigned kmax = 0;
#pragma unroll
    for (int e = 0; e < 64; e++) kmax = (keys[e] > kmax) ? keys[e] : kmax;
#pragma unroll
    for (int off = 16; off > 0; off >>= 1) {
        unsigned t = __shfl_xor_sync(0xffffffffu, kmax, off);
        kmax = (t > kmax) ? t : kmax;
    }
    const float rmax = key2float(kmax);

    // ---- Phase A: gather selected (idx, raw key) — NO exp here ----
#pragma unroll
    for (int i = 0; i < 16; i++) {
#pragma unroll
        for (int j = 0; j < 4; j++) {
            unsigned k = keys[i * 4 + j];
            if (k >= kth) {
                int p = atomicAdd(&cnt_s[wid], 1);
                if (p < 96) {
                    sidx[p] = (i * 32 + lane) * 4 + j;
                    sw[p] = __uint_as_float(k);   // stash key bits
                }
            }
        }
    }
    __syncwarp();
    int cnt = cnt_s[wid]; if (cnt > 96) cnt = 96;

    // ---- Phase B: exp only on gathered (<=3/lane), Z, normalize in place ----
    float part = 0.f;
    for (int j = lane; j < cnt; j += 32) {
        float e = __expf(key2float(__float_as_uint(sw[j])) - rmax);
        sw[j] = e;
        part += e;
    }
#pragma unroll
    for (int off = 16; off > 0; off >>= 1)
        part += __shfl_xor_sync(0xffffffffu, part, off);
    const float inv_z = 1.f / part;
    __syncwarp();
    for (int j = lane; j < cnt; j += 32) sw[j] *= inv_z;
    __syncwarp();

    // ---- Phase C: attn row = zeros, then scatter selected weights ----
    if (write_attn) {
        float4* Arow4 = (float4*)&attn[(size_t)row * NN];
        const float4 z4 = make_float4(0.f, 0.f, 0.f, 0.f);
#pragma unroll
        for (int i = 0; i < 16; i++)
            __stcs(&Arow4[i * 32 + lane], z4);
        __threadfence_block();
        __syncwarp();
        float* Arow = &attn[(size_t)row * NN];
        for (int j = lane; j < cnt; j += 32)
            Arow[sidx[j]] = sw[j];
    }

    // ---- AV: 64 dims across 32 lanes (float2/lane), ~64 selected terms ----
    const float2* Vbase = (const float2*)&g_Vh[(size_t)bh * NN * HD];
    float a0 = 0.f, a1 = 0.f;
    for (int j = 0; j < cnt; j++) {
        float wj = sw[j];
        float2 vv = Vbase[(size_t)sidx[j] * 32 + lane];
        a0 += wj * vv.x;
        a1 += wj * vv.y;
    }
    int b = bh >> 3, h = bh & 7;
    float2* Hp = (float2*)&g_H[(size_t)(b * NN + q) * DM + h * HD];
    Hp[lane] = make_float2(a0, a1);
}

// ---------------------------------------------------------------------------
extern "C" void kernel_launch(void* const* d_in, const int* in_sizes, int n_in,
                              void* d_out, int out_size)
{
    const float* q  = (const float*)d_in[0];
    const float* k  = (const float*)d_in[1];
    const float* v  = (const float*)d_in[2];
    const float* wq = (const float*)d_in[3];
    const float* bq = (const float*)d_in[4];
    const float* wk = (const float*)d_in[5];
    const float* bk = (const float*)d_in[6];
    const float* wv = (const float*)d_in[7];
    const float* bv = (const float*)d_in[8];
    const float* wo = (const float*)d_in[9];
    const float* bo = (const float*)d_in[10];

    float* out = (float*)d_out;
    const long long OUT_ELEMS  = (long long)M_TOT * DM;        // 2,097,152
    const long long ATTN_ELEMS = (long long)BH * NN * NN;      // 67,108,864

    int write_attn = 0, write_out = 1;
    float* attn_ptr = nullptr;
    if ((long long)out_size >= OUT_ELEMS + ATTN_ELEMS) {
        write_attn = 1; attn_ptr = out + OUT_ELEMS;
    } else if ((long long)out_size == ATTN_ELEMS) {
        write_attn = 1; attn_ptr = out; write_out = 0;
    }

    // fused QKV projections: grid (12, 64) = 768 blocks of 64x128
    gemm64<<<dim3(12, M_TOT / 64), 256>>>(q, k, v, wq, wk, wv, bq, bk, bv,
                                          nullptr, 0);

    scores_kernel<<<dim3(NN / 128, NN / 128, BH), 256>>>();

    topk_av_warp<<<BH * NN / 8, 256>>>(attn_ptr, write_attn);

    if (write_out)
        gemm64<<<dim3(DM / 128, M_TOT / 64), 256>>>(nullptr, nullptr, nullptr,
                                                    wo, nullptr, nullptr,
                                                    bo, nullptr, nullptr,
                                                    out, 1);
}